// round 3
// baseline (speedup 1.0000x reference)
#include <cuda_runtime.h>

#define NB 4096
#define ND 1024
#define NF 512
#define NEG_INF (-1e30f)

// ---------------- scratch (device globals; no allocations allowed) ----------
__device__ float g_proj[3][NB * NF];          // 24 MB projected modalities (filled in place)
__device__ float g_norm[3][NB];               // row L2 norms (pre-fill)
__device__ int   g_rows[3][NB];               // compacted missing-row lists
__device__ int   g_cnt[3];                    // missing counts
__device__ float g_sim[(size_t)NB * NB];      // 64 MB sim scratch (reused per modality)
__device__ float g_h[(size_t)NB * NF];        // 8 MB hidden layer

// ---------------- tiny setup kernels ----------------------------------------
__global__ void k_reset() {
    if (threadIdx.x < 3) g_cnt[threadIdx.x] = 0;
}

__global__ void k_build(const int* __restrict__ mi) {
    int i = blockIdx.x * blockDim.x + threadIdx.x;
    if (i < NB) {
        int t = mi[i];
        if (t >= 1 && t <= 3) {
            int p = atomicAdd(&g_cnt[t - 1], 1);
            g_rows[t - 1][p] = i;
        }
    }
}

// ---------------- projection GEMM: proj[z] = X_z @ W_z + b_z ----------------
// 64x64 tile, BK=16, 256 threads, 4x4 micro-tile.
__global__ void __launch_bounds__(256) k_proj(
    const float* __restrict__ A0, const float* __restrict__ A1, const float* __restrict__ A2,
    const float* __restrict__ Wl, const float* __restrict__ Wv, const float* __restrict__ Wa,
    const float* __restrict__ bl, const float* __restrict__ bv, const float* __restrict__ ba)
{
    const int z = blockIdx.z;
    const float* A    = (z == 0) ? A0 : (z == 1) ? A1 : A2;
    const float* W    = (z == 0) ? Wl : (z == 1) ? Wv : Wa;
    const float* bias = (z == 0) ? bl : (z == 1) ? bv : ba;
    float* C = g_proj[z];
    const int K = ND, N = NF;

    __shared__ float As[16][64];
    __shared__ float Bs[16][64];

    const int m0 = blockIdx.y * 64, n0 = blockIdx.x * 64;
    const int tx = threadIdx.x & 15, ty = threadIdx.x >> 4;
    const int ar = threadIdx.x >> 2, ac = (threadIdx.x & 3) * 4;   // A tile loader
    const int br = threadIdx.x >> 4, bc = (threadIdx.x & 15) * 4;  // B tile loader

    float acc[4][4] = {};

    for (int k0 = 0; k0 < K; k0 += 16) {
        float4 va = *(const float4*)(A + (size_t)(m0 + ar) * K + k0 + ac);
        As[ac + 0][ar] = va.x; As[ac + 1][ar] = va.y;
        As[ac + 2][ar] = va.z; As[ac + 3][ar] = va.w;
        float4 vb = *(const float4*)(W + (size_t)(k0 + br) * N + n0 + bc);
        *(float4*)&Bs[br][bc] = vb;
        __syncthreads();
#pragma unroll
        for (int k = 0; k < 16; k++) {
            float a[4], b[4];
            *(float4*)a = *(const float4*)&As[k][ty * 4];
            *(float4*)b = *(const float4*)&Bs[k][tx * 4];
#pragma unroll
            for (int i = 0; i < 4; i++)
#pragma unroll
                for (int j = 0; j < 4; j++) acc[i][j] += a[i] * b[j];
        }
        __syncthreads();
    }
#pragma unroll
    for (int i = 0; i < 4; i++) {
        float4 o;
        o.x = acc[i][0] + bias[n0 + tx * 4 + 0];
        o.y = acc[i][1] + bias[n0 + tx * 4 + 1];
        o.z = acc[i][2] + bias[n0 + tx * 4 + 2];
        o.w = acc[i][3] + bias[n0 + tx * 4 + 3];
        *(float4*)(C + (size_t)(m0 + ty * 4 + i) * N + n0 + tx * 4) = o;
    }
}

// ---------------- row norms (pre-fill) ---------------------------------------
__global__ void __launch_bounds__(128) k_norm() {
    const int z = blockIdx.z;
    const int warp = threadIdx.x >> 5, lane = threadIdx.x & 31;
    const int row = blockIdx.x * 4 + warp;
    const float* p = g_proj[z] + (size_t)row * NF;
    float s = 0.f;
    for (int f = lane; f < NF; f += 32) { float v = p[f]; s += v * v; }
#pragma unroll
    for (int o = 16; o; o >>= 1) s += __shfl_xor_sync(0xffffffffu, s, o);
    if (lane == 0) g_norm[z][row] = sqrtf(s);
}

// ---------------- sim GEMM (NT): sim[m, n] = <proj[rows[m]], proj[n]> --------
__global__ void __launch_bounds__(256) k_sim(int z) {
    const int cnt = g_cnt[z];
    const int m0 = blockIdx.y * 64;
    if (m0 >= cnt) return;
    const int n0 = blockIdx.x * 64;
    const float* P = g_proj[z];

    __shared__ float As[16][64];
    __shared__ float Bs[16][64];
    __shared__ int rowi[64];
    if (threadIdx.x < 64) {
        int m = m0 + threadIdx.x;
        rowi[threadIdx.x] = g_rows[z][m < cnt ? m : cnt - 1];
    }
    __syncthreads();

    const int tx = threadIdx.x & 15, ty = threadIdx.x >> 4;
    const int ar = threadIdx.x >> 2, ac = (threadIdx.x & 3) * 4;
    float acc[4][4] = {};

    for (int k0 = 0; k0 < NF; k0 += 16) {
        float4 va = *(const float4*)(P + (size_t)rowi[ar] * NF + k0 + ac);
        As[ac + 0][ar] = va.x; As[ac + 1][ar] = va.y;
        As[ac + 2][ar] = va.z; As[ac + 3][ar] = va.w;
        float4 vb = *(const float4*)(P + (size_t)(n0 + ar) * NF + k0 + ac);
        Bs[ac + 0][ar] = vb.x; Bs[ac + 1][ar] = vb.y;
        Bs[ac + 2][ar] = vb.z; Bs[ac + 3][ar] = vb.w;
        __syncthreads();
#pragma unroll
        for (int k = 0; k < 16; k++) {
            float a[4], b[4];
            *(float4*)a = *(const float4*)&As[k][ty * 4];
            *(float4*)b = *(const float4*)&Bs[k][tx * 4];
#pragma unroll
            for (int i = 0; i < 4; i++)
#pragma unroll
                for (int j = 0; j < 4; j++) acc[i][j] += a[i] * b[j];
        }
        __syncthreads();
    }
#pragma unroll
    for (int i = 0; i < 4; i++) {
        int m = m0 + ty * 4 + i;
        if (m < cnt) {
            float4 o = {acc[i][0], acc[i][1], acc[i][2], acc[i][3]};
            *(float4*)(g_sim + (size_t)m * NB + n0 + tx * 4) = o;
        }
    }
}

// ---------------- top-3 + softmax + fill -------------------------------------
__device__ __forceinline__ bool better(float v, int i, float V, int I) {
    return v > V || (v == V && i < I);  // jax top_k tie-break: lower index wins
}

__global__ void __launch_bounds__(128) k_topk(int z, const int* __restrict__ mi) {
    const int m = blockIdx.x;
    const int cnt = g_cnt[z];
    if (m >= cnt) return;
    const int r = g_rows[z][m];
    float* P = g_proj[z];
    const float* nrm = g_norm[z];
    const float ni = nrm[r];
    const float* srow = g_sim + (size_t)m * NB;

    float v0 = NEG_INF, v1 = NEG_INF, v2 = NEG_INF;
    int   i0 = NB, i1 = NB, i2 = NB;
    for (int n = threadIdx.x; n < NB; n += 128) {
        if (mi[n] == z + 1) continue;  // missing columns excluded (incl. self)
        float s = srow[n] / fmaxf(ni * nrm[n], 1e-8f);
        if (better(s, n, v0, i0)) { v2 = v1; i2 = i1; v1 = v0; i1 = i0; v0 = s; i0 = n; }
        else if (better(s, n, v1, i1)) { v2 = v1; i2 = i1; v1 = s; i1 = n; }
        else if (better(s, n, v2, i2)) { v2 = s; i2 = n; }
    }

    __shared__ float sv[384];
    __shared__ int   si[384];
    sv[threadIdx.x * 3 + 0] = v0; si[threadIdx.x * 3 + 0] = i0;
    sv[threadIdx.x * 3 + 1] = v1; si[threadIdx.x * 3 + 1] = i1;
    sv[threadIdx.x * 3 + 2] = v2; si[threadIdx.x * 3 + 2] = i2;
    __syncthreads();

    __shared__ float w[3];
    __shared__ int   bi[3];
    if (threadIdx.x == 0) {
        float b0 = NEG_INF, b1 = NEG_INF, b2 = NEG_INF;
        int   j0 = NB, j1 = NB, j2 = NB;
        for (int t = 0; t < 384; t++) {
            float s = sv[t]; int n = si[t];
            if (better(s, n, b0, j0)) { b2 = b1; j2 = j1; b1 = b0; j1 = j0; b0 = s; j0 = n; }
            else if (better(s, n, b1, j1)) { b2 = b1; j2 = j1; b1 = s; j1 = n; }
            else if (better(s, n, b2, j2)) { b2 = s; j2 = n; }
        }
        float e0 = 1.0f, e1 = expf(b1 - b0), e2 = expf(b2 - b0);
        float inv = 1.0f / (e0 + e1 + e2);
        w[0] = e0 * inv; w[1] = e1 * inv; w[2] = e2 * inv;
        bi[0] = j0; bi[1] = j1; bi[2] = j2;
    }
    __syncthreads();

    const float* f0 = P + (size_t)bi[0] * NF;
    const float* f1 = P + (size_t)bi[1] * NF;
    const float* f2 = P + (size_t)bi[2] * NF;
    const float w0 = w[0], w1 = w[1], w2 = w[2];
    for (int f = threadIdx.x; f < NF; f += 128)
        P[(size_t)r * NF + f] = w0 * f0[f] + w1 * f1[f] + w2 * f2[f];
}

// ---------------- fused concat GEMM + ReLU: h = relu([p0|p1|p2] @ W1 + b1) ---
__global__ void __launch_bounds__(256) k_h(const float* __restrict__ W1,
                                           const float* __restrict__ b1) {
    __shared__ float As[16][64];
    __shared__ float Bs[16][64];
    const int m0 = blockIdx.y * 64, n0 = blockIdx.x * 64;
    const int tx = threadIdx.x & 15, ty = threadIdx.x >> 4;
    const int ar = threadIdx.x >> 2, ac = (threadIdx.x & 3) * 4;
    const int br = threadIdx.x >> 4, bc = (threadIdx.x & 15) * 4;
    float acc[4][4] = {};

    for (int k0 = 0; k0 < 3 * NF; k0 += 16) {
        const float* A = g_proj[k0 >> 9];   // BK tile never crosses a 512 boundary
        const int kc = k0 & 511;
        float4 va = *(const float4*)(A + (size_t)(m0 + ar) * NF + kc + ac);
        As[ac + 0][ar] = va.x; As[ac + 1][ar] = va.y;
        As[ac + 2][ar] = va.z; As[ac + 3][ar] = va.w;
        float4 vb = *(const float4*)(W1 + (size_t)(k0 + br) * NF + n0 + bc);
        *(float4*)&Bs[br][bc] = vb;
        __syncthreads();
#pragma unroll
        for (int k = 0; k < 16; k++) {
            float a[4], b[4];
            *(float4*)a = *(const float4*)&As[k][ty * 4];
            *(float4*)b = *(const float4*)&Bs[k][tx * 4];
#pragma unroll
            for (int i = 0; i < 4; i++)
#pragma unroll
                for (int j = 0; j < 4; j++) acc[i][j] += a[i] * b[j];
        }
        __syncthreads();
    }
#pragma unroll
    for (int i = 0; i < 4; i++) {
        float4 o;
        o.x = fmaxf(acc[i][0] + b1[n0 + tx * 4 + 0], 0.f);
        o.y = fmaxf(acc[i][1] + b1[n0 + tx * 4 + 1], 0.f);
        o.z = fmaxf(acc[i][2] + b1[n0 + tx * 4 + 2], 0.f);
        o.w = fmaxf(acc[i][3] + b1[n0 + tx * 4 + 3], 0.f);
        *(float4*)(g_h + (size_t)(m0 + ty * 4 + i) * NF + n0 + tx * 4) = o;
    }
}

// ---------------- out[m] = h[m,:] . W2 + b2 ----------------------------------
__global__ void __launch_bounds__(128) k_out(const float* __restrict__ W2,
                                             const float* __restrict__ b2,
                                             float* __restrict__ out) {
    const int m = blockIdx.x;
    float s = 0.f;
    for (int n = threadIdx.x; n < NF; n += 128)
        s += g_h[(size_t)m * NF + n] * W2[n];
#pragma unroll
    for (int o = 16; o; o >>= 1) s += __shfl_xor_sync(0xffffffffu, s, o);
    __shared__ float ps[4];
    if ((threadIdx.x & 31) == 0) ps[threadIdx.x >> 5] = s;
    __syncthreads();
    if (threadIdx.x == 0) out[m] = ps[0] + ps[1] + ps[2] + ps[3] + b2[0];
}

// ---------------- launcher ----------------------------------------------------
extern "C" void kernel_launch(void* const* d_in, const int* in_sizes, int n_in,
                              void* d_out, int out_size) {
    const float* lang = (const float*)d_in[0];
    const float* vid  = (const float*)d_in[1];
    const float* aud  = (const float*)d_in[2];
    const int*   mi   = (const int*)d_in[3];
    const float* Wl   = (const float*)d_in[4];
    const float* bl   = (const float*)d_in[5];
    const float* Wv   = (const float*)d_in[6];
    const float* bv   = (const float*)d_in[7];
    const float* Wa   = (const float*)d_in[8];
    const float* ba   = (const float*)d_in[9];
    const float* W1   = (const float*)d_in[10];
    const float* b1   = (const float*)d_in[11];
    const float* W2   = (const float*)d_in[12];
    const float* b2   = (const float*)d_in[13];
    float* out = (float*)d_out;

    k_reset<<<1, 32>>>();
    k_build<<<NB / 256, 256>>>(mi);
    k_proj<<<dim3(NF / 64, NB / 64, 3), 256>>>(lang, vid, aud, Wl, Wv, Wa, bl, bv, ba);
    k_norm<<<dim3(NB / 4, 1, 3), 128>>>();
    for (int z = 0; z < 3; z++) {
        k_sim<<<dim3(NB / 64, NB / 64), 256>>>(z);
        k_topk<<<NB, 128>>>(z, mi);
    }
    k_h<<<dim3(NF / 64, NB / 64), 256>>>(W1, b1);
    k_out<<<NB, 128>>>(W2, b2, out);
}

// round 4
// speedup vs baseline: 2.2173x; 2.2173x over previous
#include <cuda_runtime.h>
#include <cuda_bf16.h>
#include <cstdint>

#define NB 4096
#define ND 1024
#define NF 512
#define NEG_INF (-1e30f)

typedef __nv_bfloat16 bf16;

// ---------------- scratch (device globals; no allocations allowed) ----------
__device__ float g_proj[3][NB * NF];          // fp32 projections (filled in place)
__device__ float g_norm[3][NB];
__device__ int   g_rows[3][NB];
__device__ int   g_cnt[3];
__device__ float g_sim[(size_t)NB * NB];
__device__ float g_h[(size_t)NB * NF];

__device__ bf16 g_xh[3][NB * ND], g_xl[3][NB * ND];   // split inputs
__device__ bf16 g_wh[3][ND * NF], g_wl[3][ND * NF];   // split proj weights
__device__ bf16 g_w1h[3 * NF * NF], g_w1l[3 * NF * NF];
__device__ bf16 g_ph[3][NB * NF], g_pl[3][NB * NF];   // split projections

// ---------------- PTX helpers ------------------------------------------------
__device__ __forceinline__ uint32_t s2u(const void* p) {
    return (uint32_t)__cvta_generic_to_shared(p);
}
__device__ __forceinline__ void cpa(uint32_t dst, const void* src) {
    asm volatile("cp.async.cg.shared.global [%0], [%1], 16;\n" :: "r"(dst), "l"(src));
}
__device__ __forceinline__ void cpcommit() { asm volatile("cp.async.commit_group;\n"); }
__device__ __forceinline__ void cpwait1()  { asm volatile("cp.async.wait_group 1;\n"); }
__device__ __forceinline__ void cpwait0()  { asm volatile("cp.async.wait_group 0;\n"); }
__device__ __forceinline__ void ldsm4(uint32_t* r, uint32_t a) {
    asm volatile("ldmatrix.sync.aligned.m8n8.x4.shared.b16 {%0,%1,%2,%3}, [%4];\n"
                 : "=r"(r[0]), "=r"(r[1]), "=r"(r[2]), "=r"(r[3]) : "r"(a));
}
__device__ __forceinline__ void ldsm4t(uint32_t* r, uint32_t a) {
    asm volatile("ldmatrix.sync.aligned.m8n8.x4.trans.shared.b16 {%0,%1,%2,%3}, [%4];\n"
                 : "=r"(r[0]), "=r"(r[1]), "=r"(r[2]), "=r"(r[3]) : "r"(a));
}
__device__ __forceinline__ void mma_bf16(float* c, const uint32_t* a, const uint32_t* b) {
    asm volatile("mma.sync.aligned.m16n8k16.row.col.f32.bf16.bf16.f32 "
                 "{%0,%1,%2,%3},{%4,%5,%6,%7},{%8,%9},{%0,%1,%2,%3};\n"
                 : "+f"(c[0]), "+f"(c[1]), "+f"(c[2]), "+f"(c[3])
                 : "r"(a[0]), "r"(a[1]), "r"(a[2]), "r"(a[3]), "r"(b[0]), "r"(b[1]));
}
// 128B smem rows, xor-swizzle of 16B chunks -> conflict-free ldmatrix
__device__ __forceinline__ uint32_t swz(uint32_t row, uint32_t chunk) {
    return row * 128u + ((chunk ^ (row & 7u)) * 16u);
}

// smem stage layout: A tile 128x64 bf16 m-major (16KB), B tile 64x64 bf16 (8KB)
#define ST_A 16384
#define ST_SZ 24576

// compute one BK=64 stage: A m-major (non-trans ldsm), B k-major (trans ldsm)  [NN]
__device__ __forceinline__ void stage_nn(uint32_t aB, uint32_t bB, int wm, int wn,
                                         int lane, float (&acc)[2][4][4]) {
#pragma unroll
    for (int ks = 0; ks < 4; ks++) {
        uint32_t af[2][4];
#pragma unroll
        for (int mt = 0; mt < 2; mt++) {
            uint32_t m_l = wm * 32 + mt * 16 + (lane & 15);
            ldsm4(af[mt], aB + swz(m_l, ks * 2 + (lane >> 4)));
        }
        uint32_t bfr[4][2];
#pragma unroll
        for (int j = 0; j < 2; j++) {
            uint32_t k_l = ks * 16 + (lane & 15);
            uint32_t r[4];
            ldsm4t(r, bB + swz(k_l, wn * 4 + j * 2 + (lane >> 4)));
            bfr[j * 2][0] = r[0]; bfr[j * 2][1] = r[1];
            bfr[j * 2 + 1][0] = r[2]; bfr[j * 2 + 1][1] = r[3];
        }
#pragma unroll
        for (int mt = 0; mt < 2; mt++)
#pragma unroll
            for (int nt = 0; nt < 4; nt++) mma_bf16(acc[mt][nt], af[mt], bfr[nt]);
    }
}

// compute one stage: A m-major, B n-major (non-trans ldsm)  [NT: C = A @ B^T]
__device__ __forceinline__ void stage_nt(uint32_t aB, uint32_t bB, int wm, int wn,
                                         int lane, float (&acc)[2][4][4]) {
#pragma unroll
    for (int ks = 0; ks < 4; ks++) {
        uint32_t af[2][4];
#pragma unroll
        for (int mt = 0; mt < 2; mt++) {
            uint32_t m_l = wm * 32 + mt * 16 + (lane & 15);
            ldsm4(af[mt], aB + swz(m_l, ks * 2 + (lane >> 4)));
        }
        uint32_t bfr[4][2];
#pragma unroll
        for (int j = 0; j < 2; j++) {
            uint32_t n_l = wn * 32 + j * 16 + (lane & 7) + ((lane >> 4) << 3);
            uint32_t r[4];
            ldsm4(r, bB + swz(n_l, ks * 2 + ((lane >> 3) & 1)));
            bfr[j * 2][0] = r[0]; bfr[j * 2][1] = r[1];
            bfr[j * 2 + 1][0] = r[2]; bfr[j * 2 + 1][1] = r[3];
        }
#pragma unroll
        for (int mt = 0; mt < 2; mt++)
#pragma unroll
            for (int nt = 0; nt < 4; nt++) mma_bf16(acc[mt][nt], af[mt], bfr[nt]);
    }
}

// ---------------- tiny setup kernels -----------------------------------------
__global__ void k_reset() { if (threadIdx.x < 3) g_cnt[threadIdx.x] = 0; }

__global__ void k_build(const int* __restrict__ mi) {
    int i = blockIdx.x * blockDim.x + threadIdx.x;
    if (i < NB) {
        int t = mi[i];
        if (t >= 1 && t <= 3) { int p = atomicAdd(&g_cnt[t - 1], 1); g_rows[t - 1][p] = i; }
    }
}

// fp32 -> bf16 hi/lo split
__global__ void __launch_bounds__(256) k_split(const float* __restrict__ src, int which, int n4) {
    bf16 *h, *l;
    switch (which) {
        case 0: h = g_xh[0]; l = g_xl[0]; break;
        case 1: h = g_xh[1]; l = g_xl[1]; break;
        case 2: h = g_xh[2]; l = g_xl[2]; break;
        case 3: h = g_wh[0]; l = g_wl[0]; break;
        case 4: h = g_wh[1]; l = g_wl[1]; break;
        case 5: h = g_wh[2]; l = g_wl[2]; break;
        default: h = g_w1h;  l = g_w1l;  break;
    }
    int i = blockIdx.x * 256 + threadIdx.x;
    if (i >= n4) return;
    float4 v = ((const float4*)src)[i];
    bf16 h0 = __float2bfloat16(v.x), h1 = __float2bfloat16(v.y);
    bf16 h2 = __float2bfloat16(v.z), h3 = __float2bfloat16(v.w);
    __nv_bfloat162* H = (__nv_bfloat162*)h;
    __nv_bfloat162* L = (__nv_bfloat162*)l;
    H[2 * i]     = __halves2bfloat162(h0, h1);
    H[2 * i + 1] = __halves2bfloat162(h2, h3);
    L[2 * i]     = __halves2bfloat162(__float2bfloat16(v.x - __bfloat162float(h0)),
                                      __float2bfloat16(v.y - __bfloat162float(h1)));
    L[2 * i + 1] = __halves2bfloat162(__float2bfloat16(v.z - __bfloat162float(h2)),
                                      __float2bfloat16(v.w - __bfloat162float(h3)));
}

// ---------------- projection GEMM (tensor cores, 3-term bf16 split) ----------
__global__ void __launch_bounds__(256) k_proj_mma(const float* __restrict__ bl,
                                                  const float* __restrict__ bv,
                                                  const float* __restrict__ ba) {
    const int z = blockIdx.z;
    const bf16* Ah = g_xh[z]; const bf16* Al = g_xl[z];
    const bf16* Bh = g_wh[z]; const bf16* Bl = g_wl[z];
    const float* bias = (z == 0) ? bl : (z == 1) ? bv : ba;
    const int m0 = blockIdx.y * 128, n0 = blockIdx.x * 64;

    __shared__ __align__(16) char sm[2 * ST_SZ];
    const uint32_t sb = s2u(sm);
    const int tid = threadIdx.x, lane = tid & 31, warp = tid >> 5;
    const int wm = warp & 3, wn = warp >> 2;

    auto load = [&](int it, int st) {
        int ph = it >> 4, kk = (it & 15) << 6;
        const bf16* Ag = (ph == 1) ? Al : Ah;
        const bf16* Bg = (ph == 2) ? Bl : Bh;
        uint32_t aB = sb + st * ST_SZ, bB = aB + ST_A;
#pragma unroll
        for (int i = 0; i < 4; i++) {
            int c = tid + i * 256, m = c >> 3, k8 = c & 7;
            cpa(aB + swz(m, k8), Ag + (size_t)(m0 + m) * ND + kk + k8 * 8);
        }
#pragma unroll
        for (int i = 0; i < 2; i++) {
            int c = tid + i * 256, k = c >> 3, n8 = c & 7;
            cpa(bB + swz(k, n8), Bg + (size_t)(kk + k) * NF + n0 + n8 * 8);
        }
        cpcommit();
    };

    float acc[2][4][4] = {};
    load(0, 0);
    const int ITERS = 48;  // 3 phases x 16 BK-tiles
    for (int it = 0; it < ITERS; it++) {
        if (it + 1 < ITERS) { load(it + 1, (it + 1) & 1); cpwait1(); } else cpwait0();
        __syncthreads();
        uint32_t aB = sb + (it & 1) * ST_SZ;
        stage_nn(aB, aB + ST_A, wm, wn, lane, acc);
        __syncthreads();
    }

    float* C = g_proj[z]; bf16* Ph = g_ph[z]; bf16* Pl = g_pl[z];
    int g = lane >> 2, tg = lane & 3;
#pragma unroll
    for (int mt = 0; mt < 2; mt++)
#pragma unroll
        for (int nt = 0; nt < 4; nt++) {
            int col = n0 + wn * 32 + nt * 8 + tg * 2;
            float bz0 = bias[col], bz1 = bias[col + 1];
#pragma unroll
            for (int hh = 0; hh < 2; hh++) {
                int row = m0 + wm * 32 + mt * 16 + g + hh * 8;
                float v0 = acc[mt][nt][hh * 2 + 0] + bz0;
                float v1 = acc[mt][nt][hh * 2 + 1] + bz1;
                size_t off = (size_t)row * NF + col;
                *(float2*)(C + off) = make_float2(v0, v1);
                bf16 p0 = __float2bfloat16(v0), p1 = __float2bfloat16(v1);
                *(__nv_bfloat162*)(Ph + off) = __halves2bfloat162(p0, p1);
                *(__nv_bfloat162*)(Pl + off) = __halves2bfloat162(
                    __float2bfloat16(v0 - __bfloat162float(p0)),
                    __float2bfloat16(v1 - __bfloat162float(p1)));
            }
        }
}

// ---------------- row norms ---------------------------------------------------
__global__ void __launch_bounds__(256) k_norm() {
    const int z = blockIdx.z;
    const int warp = threadIdx.x >> 5, lane = threadIdx.x & 31;
    const int row = blockIdx.x * 8 + warp;
    const float4* p = (const float4*)(g_proj[z] + (size_t)row * NF);
    float s = 0.f;
#pragma unroll
    for (int i = 0; i < 4; i++) {
        float4 v = p[lane + i * 32];
        s += v.x * v.x + v.y * v.y + v.z * v.z + v.w * v.w;
    }
#pragma unroll
    for (int o = 16; o; o >>= 1) s += __shfl_xor_sync(0xffffffffu, s, o);
    if (lane == 0) g_norm[z][row] = sqrtf(s);
}

// ---------------- sim GEMM (NT, gathered missing rows, tensor cores) ---------
__global__ void __launch_bounds__(256) k_sim_mma(int z) {
    const int cnt = g_cnt[z];
    const int m0 = blockIdx.y * 128;
    if (m0 >= cnt) return;
    const int n0 = blockIdx.x * 64;
    const bf16* Ph = g_ph[z]; const bf16* Pl = g_pl[z];

    __shared__ __align__(16) char sm[2 * ST_SZ];
    const uint32_t sb = s2u(sm);
    const int tid = threadIdx.x, lane = tid & 31, warp = tid >> 5;
    const int wm = warp & 3, wn = warp >> 2;

    auto load = [&](int it, int st) {
        int ph = it >> 3, kk = (it & 7) << 6;
        const bf16* Ag = (ph == 1) ? Pl : Ph;
        const bf16* Bg = (ph == 2) ? Pl : Ph;
        uint32_t aB = sb + st * ST_SZ, bB = aB + ST_A;
#pragma unroll
        for (int i = 0; i < 4; i++) {
            int c = tid + i * 256, m = c >> 3, k8 = c & 7;
            int mm = m0 + m; if (mm >= cnt) mm = cnt - 1;
            int row = g_rows[z][mm];
            cpa(aB + swz(m, k8), Ag + (size_t)row * NF + kk + k8 * 8);
        }
#pragma unroll
        for (int i = 0; i < 2; i++) {
            int c = tid + i * 256, n = c >> 3, k8 = c & 7;
            cpa(bB + swz(n, k8), Bg + (size_t)(n0 + n) * NF + kk + k8 * 8);
        }
        cpcommit();
    };

    float acc[2][4][4] = {};
    load(0, 0);
    const int ITERS = 24;  // 3 phases x 8 BK-tiles
    for (int it = 0; it < ITERS; it++) {
        if (it + 1 < ITERS) { load(it + 1, (it + 1) & 1); cpwait1(); } else cpwait0();
        __syncthreads();
        uint32_t aB = sb + (it & 1) * ST_SZ;
        stage_nt(aB, aB + ST_A, wm, wn, lane, acc);
        __syncthreads();
    }

    int g = lane >> 2, tg = lane & 3;
#pragma unroll
    for (int mt = 0; mt < 2; mt++)
#pragma unroll
        for (int nt = 0; nt < 4; nt++) {
            int col = n0 + wn * 32 + nt * 8 + tg * 2;
#pragma unroll
            for (int hh = 0; hh < 2; hh++) {
                int m = m0 + wm * 32 + mt * 16 + g + hh * 8;
                if (m < cnt)
                    *(float2*)(g_sim + (size_t)m * NB + col) =
                        make_float2(acc[mt][nt][hh * 2 + 0], acc[mt][nt][hh * 2 + 1]);
            }
        }
}

// ---------------- top-3 + softmax + fill (also refreshes bf16 splits) --------
__device__ __forceinline__ bool better(float v, int i, float V, int I) {
    return v > V || (v == V && i < I);
}

__global__ void __launch_bounds__(128) k_topk(int z, const int* __restrict__ mi) {
    const int m = blockIdx.x;
    const int cnt = g_cnt[z];
    if (m >= cnt) return;
    const int r = g_rows[z][m];
    float* P = g_proj[z];
    bf16* Ph = g_ph[z]; bf16* Pl = g_pl[z];
    const float* nrm = g_norm[z];
    const float ni = nrm[r];
    const float* srow = g_sim + (size_t)m * NB;

    float v0 = NEG_INF, v1 = NEG_INF, v2 = NEG_INF;
    int   i0 = NB, i1 = NB, i2 = NB;
    for (int n = threadIdx.x; n < NB; n += 128) {
        if (mi[n] == z + 1) continue;
        float s = srow[n] / fmaxf(ni * nrm[n], 1e-8f);
        if (better(s, n, v0, i0)) { v2 = v1; i2 = i1; v1 = v0; i1 = i0; v0 = s; i0 = n; }
        else if (better(s, n, v1, i1)) { v2 = v1; i2 = i1; v1 = s; i1 = n; }
        else if (better(s, n, v2, i2)) { v2 = s; i2 = n; }
    }

    __shared__ float sv[384];
    __shared__ int   si[384];
    sv[threadIdx.x * 3 + 0] = v0; si[threadIdx.x * 3 + 0] = i0;
    sv[threadIdx.x * 3 + 1] = v1; si[threadIdx.x * 3 + 1] = i1;
    sv[threadIdx.x * 3 + 2] = v2; si[threadIdx.x * 3 + 2] = i2;
    __syncthreads();

    __shared__ float w[3];
    __shared__ int   bi[3];
    if (threadIdx.x == 0) {
        float b0 = NEG_INF, b1 = NEG_INF, b2 = NEG_INF;
        int   j0 = NB, j1 = NB, j2 = NB;
        for (int t = 0; t < 384; t++) {
            float s = sv[t]; int n = si[t];
            if (better(s, n, b0, j0)) { b2 = b1; j2 = j1; b1 = b0; j1 = j0; b0 = s; j0 = n; }
            else if (better(s, n, b1, j1)) { b2 = b1; j2 = j1; b1 = s; j1 = n; }
            else if (better(s, n, b2, j2)) { b2 = s; j2 = n; }
        }
        float e0 = 1.0f, e1 = expf(b1 - b0), e2 = expf(b2 - b0);
        float inv = 1.0f / (e0 + e1 + e2);
        w[0] = e0 * inv; w[1] = e1 * inv; w[2] = e2 * inv;
        bi[0] = j0; bi[1] = j1; bi[2] = j2;
    }
    __syncthreads();

    const float* f0 = P + (size_t)bi[0] * NF;
    const float* f1 = P + (size_t)bi[1] * NF;
    const float* f2 = P + (size_t)bi[2] * NF;
    const float w0 = w[0], w1 = w[1], w2 = w[2];
    for (int f = threadIdx.x; f < NF; f += 128) {
        float v = w0 * f0[f] + w1 * f1[f] + w2 * f2[f];
        size_t off = (size_t)r * NF + f;
        P[off] = v;
        bf16 hh = __float2bfloat16(v);
        Ph[off] = hh;
        Pl[off] = __float2bfloat16(v - __bfloat162float(hh));
    }
}

// ---------------- fused concat GEMM + ReLU (tensor cores) --------------------
__global__ void __launch_bounds__(256) k_h_mma(const float* __restrict__ b1) {
    const int m0 = blockIdx.y * 128, n0 = blockIdx.x * 64;
    __shared__ __align__(16) char sm[2 * ST_SZ];
    const uint32_t sb = s2u(sm);
    const int tid = threadIdx.x, lane = tid & 31, warp = tid >> 5;
    const int wm = warp & 3, wn = warp >> 2;

    auto load = [&](int it, int st) {
        int ph = it / 24, rrem = it % 24;
        int mod = rrem >> 3, kk = (rrem & 7) << 6;
        const bf16* Ag = (ph == 1) ? g_pl[mod] : g_ph[mod];
        const bf16* Bg = (ph == 2) ? g_w1l : g_w1h;
        uint32_t aB = sb + st * ST_SZ, bB = aB + ST_A;
#pragma unroll
        for (int i = 0; i < 4; i++) {
            int c = tid + i * 256, m = c >> 3, k8 = c & 7;
            cpa(aB + swz(m, k8), Ag + (size_t)(m0 + m) * NF + kk + k8 * 8);
        }
#pragma unroll
        for (int i = 0; i < 2; i++) {
            int c = tid + i * 256, k = c >> 3, n8 = c & 7;
            cpa(bB + swz(k, n8), Bg + (size_t)(mod * NF + kk + k) * NF + n0 + n8 * 8);
        }
        cpcommit();
    };

    float acc[2][4][4] = {};
    load(0, 0);
    const int ITERS = 72;  // 3 phases x 3 modalities x 8 BK-tiles
    for (int it = 0; it < ITERS; it++) {
        if (it + 1 < ITERS) { load(it + 1, (it + 1) & 1); cpwait1(); } else cpwait0();
        __syncthreads();
        uint32_t aB = sb + (it & 1) * ST_SZ;
        stage_nn(aB, aB + ST_A, wm, wn, lane, acc);
        __syncthreads();
    }

    int g = lane >> 2, tg = lane & 3;
#pragma unroll
    for (int mt = 0; mt < 2; mt++)
#pragma unroll
        for (int nt = 0; nt < 4; nt++) {
            int col = n0 + wn * 32 + nt * 8 + tg * 2;
            float bz0 = b1[col], bz1 = b1[col + 1];
#pragma unroll
            for (int hh = 0; hh < 2; hh++) {
                int row = m0 + wm * 32 + mt * 16 + g + hh * 8;
                float v0 = fmaxf(acc[mt][nt][hh * 2 + 0] + bz0, 0.f);
                float v1 = fmaxf(acc[mt][nt][hh * 2 + 1] + bz1, 0.f);
                *(float2*)(g_h + (size_t)row * NF + col) = make_float2(v0, v1);
            }
        }
}

// ---------------- out[m] = h[m,:] . W2 + b2 ----------------------------------
__global__ void __launch_bounds__(128) k_out(const float* __restrict__ W2,
                                             const float* __restrict__ b2,
                                             float* __restrict__ out) {
    const int m = blockIdx.x;
    float s = 0.f;
    for (int n = threadIdx.x; n < NF; n += 128)
        s += g_h[(size_t)m * NF + n] * W2[n];
#pragma unroll
    for (int o = 16; o; o >>= 1) s += __shfl_xor_sync(0xffffffffu, s, o);
    __shared__ float ps[4];
    if ((threadIdx.x & 31) == 0) ps[threadIdx.x >> 5] = s;
    __syncthreads();
    if (threadIdx.x == 0) out[m] = ps[0] + ps[1] + ps[2] + ps[3] + b2[0];
}

// ---------------- launcher ----------------------------------------------------
extern "C" void kernel_launch(void* const* d_in, const int* in_sizes, int n_in,
                              void* d_out, int out_size) {
    const float* lang = (const float*)d_in[0];
    const float* vid  = (const float*)d_in[1];
    const float* aud  = (const float*)d_in[2];
    const int*   mi   = (const int*)d_in[3];
    const float* Wl   = (const float*)d_in[4];
    const float* bl   = (const float*)d_in[5];
    const float* Wv   = (const float*)d_in[6];
    const float* bv   = (const float*)d_in[7];
    const float* Wa   = (const float*)d_in[8];
    const float* ba   = (const float*)d_in[9];
    const float* W1   = (const float*)d_in[10];
    const float* b1   = (const float*)d_in[11];
    const float* W2   = (const float*)d_in[12];
    const float* b2   = (const float*)d_in[13];
    float* out = (float*)d_out;

    k_reset<<<1, 32>>>();
    k_build<<<NB / 256, 256>>>(mi);

    k_split<<<(NB * ND / 4) / 256, 256>>>(lang, 0, NB * ND / 4);
    k_split<<<(NB * ND / 4) / 256, 256>>>(vid,  1, NB * ND / 4);
    k_split<<<(NB * ND / 4) / 256, 256>>>(aud,  2, NB * ND / 4);
    k_split<<<(ND * NF / 4) / 256, 256>>>(Wl,   3, ND * NF / 4);
    k_split<<<(ND * NF / 4) / 256, 256>>>(Wv,   4, ND * NF / 4);
    k_split<<<(ND * NF / 4) / 256, 256>>>(Wa,   5, ND * NF / 4);
    k_split<<<(3 * NF * NF / 4) / 256, 256>>>(W1, 6, 3 * NF * NF / 4);

    k_proj_mma<<<dim3(NF / 64, NB / 128, 3), 256>>>(bl, bv, ba);
    k_norm<<<dim3(NB / 8, 1, 3), 256>>>();

    for (int z = 0; z < 3; z++) {
        k_sim_mma<<<dim3(NB / 64, NB / 128), 256>>>(z);
        k_topk<<<NB, 128>>>(z, mi);
    }

    k_h_mma<<<dim3(NF / 64, NB / 128), 256>>>(b1);
    k_out<<<NB, 128>>>(W2, b2, out);
}

// round 7
// speedup vs baseline: 2.7103x; 1.2223x over previous
#include <cuda_runtime.h>
#include <cuda_fp16.h>
#include <cstdint>

#define NB 4096
#define ND 1024
#define NF 512
#define NEG_INF (-1e30f)
#define SCL 2048.0f
#define INV_SCL (1.0f / 2048.0f)

typedef __half hf;

// ---------------- scratch (device globals; no allocations allowed) ----------
__device__ float g_proj[3][NB * NF];          // fp32 projections (filled in place)
__device__ float g_norm[3][NB];
__device__ int   g_rows[3][NB];
__device__ int   g_cnt[3];
__device__ float g_sim[(size_t)NB * NB];
__device__ float g_h[(size_t)NB * NF];

__device__ hf g_xh[3][NB * ND], g_xl[3][NB * ND];   // fp16 scaled splits of inputs
__device__ hf g_wh[3][ND * NF], g_wl[3][ND * NF];   // proj weights
__device__ hf g_w1h[3 * NF * NF], g_w1l[3 * NF * NF];
__device__ hf g_ph[3][NB * NF], g_pl[3][NB * NF];   // projections

// ---------------- PTX helpers ------------------------------------------------
__device__ __forceinline__ uint32_t s2u(const void* p) {
    return (uint32_t)__cvta_generic_to_shared(p);
}
__device__ __forceinline__ void cpa(uint32_t dst, const void* src) {
    asm volatile("cp.async.cg.shared.global [%0], [%1], 16;\n" :: "r"(dst), "l"(src));
}
__device__ __forceinline__ void cpcommit() { asm volatile("cp.async.commit_group;\n"); }
__device__ __forceinline__ void cpwait1()  { asm volatile("cp.async.wait_group 1;\n"); }
__device__ __forceinline__ void cpwait0()  { asm volatile("cp.async.wait_group 0;\n"); }
__device__ __forceinline__ void ldsm4(uint32_t* r, uint32_t a) {
    asm volatile("ldmatrix.sync.aligned.m8n8.x4.shared.b16 {%0,%1,%2,%3}, [%4];\n"
                 : "=r"(r[0]), "=r"(r[1]), "=r"(r[2]), "=r"(r[3]) : "r"(a));
}
__device__ __forceinline__ void ldsm4t(uint32_t* r, uint32_t a) {
    asm volatile("ldmatrix.sync.aligned.m8n8.x4.trans.shared.b16 {%0,%1,%2,%3}, [%4];\n"
                 : "=r"(r[0]), "=r"(r[1]), "=r"(r[2]), "=r"(r[3]) : "r"(a));
}
__device__ __forceinline__ void mma_f16(float* c, const uint32_t* a, const uint32_t* b) {
    asm volatile("mma.sync.aligned.m16n8k16.row.col.f32.f16.f16.f32 "
                 "{%0,%1,%2,%3},{%4,%5,%6,%7},{%8,%9},{%0,%1,%2,%3};\n"
                 : "+f"(c[0]), "+f"(c[1]), "+f"(c[2]), "+f"(c[3])
                 : "r"(a[0]), "r"(a[1]), "r"(a[2]), "r"(a[3]), "r"(b[0]), "r"(b[1]));
}
// 128B smem rows, xor-swizzle of 16B chunks -> conflict-free ldmatrix
__device__ __forceinline__ uint32_t swz(uint32_t row, uint32_t chunk) {
    return row * 128u + ((chunk ^ (row & 7u)) * 16u);
}

// fused-stage smem layout (per stage): AH 16KB | AL 16KB | BH 8KB | BL 8KB
#define OFF_AL 16384
#define OFF_BH 32768
#define OFF_BL 40960
#define STG    49152
#define DSM    (2 * STG)

// one BK=64 stage: acc1 += Ah*Bh ; acc2 += Al*Bh + Ah*Bl  (acc2 scaled 2^-11 later)
// NN: A m-major (non-trans), B k-major (trans ldsm)
__device__ __forceinline__ void stage3_nn(uint32_t base, int wm, int wn, int lane,
                                          float (&acc1)[2][4][4], float (&acc2)[2][4][4]) {
#pragma unroll
    for (int ks = 0; ks < 4; ks++) {
        uint32_t ah[2][4], al[2][4];
#pragma unroll
        for (int mt = 0; mt < 2; mt++) {
            uint32_t m_l = wm * 32 + mt * 16 + (lane & 15);
            uint32_t c = ks * 2 + (lane >> 4);
            ldsm4(ah[mt], base + swz(m_l, c));
            ldsm4(al[mt], base + OFF_AL + swz(m_l, c));
        }
        uint32_t bh[4][2], bl[4][2];
#pragma unroll
        for (int j = 0; j < 2; j++) {
            uint32_t k_l = ks * 16 + (lane & 15);
            uint32_t c = wn * 4 + j * 2 + (lane >> 4);
            uint32_t r[4];
            ldsm4t(r, base + OFF_BH + swz(k_l, c));
            bh[j * 2][0] = r[0]; bh[j * 2][1] = r[1];
            bh[j * 2 + 1][0] = r[2]; bh[j * 2 + 1][1] = r[3];
            ldsm4t(r, base + OFF_BL + swz(k_l, c));
            bl[j * 2][0] = r[0]; bl[j * 2][1] = r[1];
            bl[j * 2 + 1][0] = r[2]; bl[j * 2 + 1][1] = r[3];
        }
#pragma unroll
        for (int mt = 0; mt < 2; mt++)
#pragma unroll
            for (int nt = 0; nt < 4; nt++) {
                mma_f16(acc1[mt][nt], ah[mt], bh[nt]);
                mma_f16(acc2[mt][nt], al[mt], bh[nt]);
                mma_f16(acc2[mt][nt], ah[mt], bl[nt]);
            }
    }
}

// NT: A m-major, B n-major (non-trans ldsm).  C = A @ B^T
__device__ __forceinline__ void stage3_nt(uint32_t base, int wm, int wn, int lane,
                                          float (&acc1)[2][4][4], float (&acc2)[2][4][4]) {
#pragma unroll
    for (int ks = 0; ks < 4; ks++) {
        uint32_t ah[2][4], al[2][4];
#pragma unroll
        for (int mt = 0; mt < 2; mt++) {
            uint32_t m_l = wm * 32 + mt * 16 + (lane & 15);
            uint32_t c = ks * 2 + (lane >> 4);
            ldsm4(ah[mt], base + swz(m_l, c));
            ldsm4(al[mt], base + OFF_AL + swz(m_l, c));
        }
        uint32_t bh[4][2], bl[4][2];
#pragma unroll
        for (int j = 0; j < 2; j++) {
            uint32_t n_l = wn * 32 + j * 16 + (lane & 7) + ((lane >> 4) << 3);
            uint32_t c = ks * 2 + ((lane >> 3) & 1);
            uint32_t r[4];
            ldsm4(r, base + OFF_BH + swz(n_l, c));
            bh[j * 2][0] = r[0]; bh[j * 2][1] = r[1];
            bh[j * 2 + 1][0] = r[2]; bh[j * 2 + 1][1] = r[3];
            ldsm4(r, base + OFF_BL + swz(n_l, c));
            bl[j * 2][0] = r[0]; bl[j * 2][1] = r[1];
            bl[j * 2 + 1][0] = r[2]; bl[j * 2 + 1][1] = r[3];
        }
#pragma unroll
        for (int mt = 0; mt < 2; mt++)
#pragma unroll
            for (int nt = 0; nt < 4; nt++) {
                mma_f16(acc1[mt][nt], ah[mt], bh[nt]);
                mma_f16(acc2[mt][nt], al[mt], bh[nt]);
                mma_f16(acc2[mt][nt], ah[mt], bl[nt]);
            }
    }
}

// ---------------- tiny setup kernels -----------------------------------------
__global__ void k_reset() { if (threadIdx.x < 3) g_cnt[threadIdx.x] = 0; }

__global__ void k_build(const int* __restrict__ mi) {
    int i = blockIdx.x * blockDim.x + threadIdx.x;
    if (i < NB) {
        int t = mi[i];
        if (t >= 1 && t <= 3) { int p = atomicAdd(&g_cnt[t - 1], 1); g_rows[t - 1][p] = i; }
    }
}

// fp32 -> fp16 scaled hi/lo split:  x = h + l/2048,  h=fp16(x), l=fp16((x-h)*2048)
__global__ void __launch_bounds__(256) k_split(const float* __restrict__ src, int which, int n4) {
    hf *h, *l;
    switch (which) {
        case 0: h = g_xh[0]; l = g_xl[0]; break;
        case 1: h = g_xh[1]; l = g_xl[1]; break;
        case 2: h = g_xh[2]; l = g_xl[2]; break;
        case 3: h = g_wh[0]; l = g_wl[0]; break;
        case 4: h = g_wh[1]; l = g_wl[1]; break;
        case 5: h = g_wh[2]; l = g_wl[2]; break;
        default: h = g_w1h;  l = g_w1l;  break;
    }
    int i = blockIdx.x * 256 + threadIdx.x;
    if (i >= n4) return;
    float4 v = ((const float4*)src)[i];
    hf h0 = __float2half_rn(v.x), h1 = __float2half_rn(v.y);
    hf h2 = __float2half_rn(v.z), h3 = __float2half_rn(v.w);
    __half2* H = (__half2*)h;
    __half2* L = (__half2*)l;
    H[2 * i]     = __halves2half2(h0, h1);
    H[2 * i + 1] = __halves2half2(h2, h3);
    L[2 * i]     = __halves2half2(__float2half_rn((v.x - __half2float(h0)) * SCL),
                                  __float2half_rn((v.y - __half2float(h1)) * SCL));
    L[2 * i + 1] = __halves2half2(__float2half_rn((v.z - __half2float(h2)) * SCL),
                                  __float2half_rn((v.w - __half2float(h3)) * SCL));
}

__device__ __forceinline__ void split2(hf* Ph, hf* Pl, size_t off, float v0, float v1) {
    hf h0 = __float2half_rn(v0), h1 = __float2half_rn(v1);
    *(__half2*)(Ph + off) = __halves2half2(h0, h1);
    *(__half2*)(Pl + off) = __halves2half2(
        __float2half_rn((v0 - __half2float(h0)) * SCL),
        __float2half_rn((v1 - __half2float(h1)) * SCL));
}

// ---------------- projection GEMM (fused dual-acc fp16 split) ----------------
__global__ void __launch_bounds__(256) k_proj_mma(const float* __restrict__ bl,
                                                  const float* __restrict__ bv,
                                                  const float* __restrict__ ba) {
    const int z = blockIdx.z;
    const hf* Ah = g_xh[z]; const hf* Al = g_xl[z];
    const hf* Bh = g_wh[z]; const hf* Bl = g_wl[z];
    const float* bias = (z == 0) ? bl : (z == 1) ? bv : ba;
    const int m0 = blockIdx.y * 128, n0 = blockIdx.x * 64;

    extern __shared__ __align__(16) char sm[];
    const uint32_t sb = s2u(sm);
    const int tid = threadIdx.x, lane = tid & 31, warp = tid >> 5;
    const int wm = warp & 3, wn = warp >> 2;

    auto load = [&](int it, int st) {
        const int kk = it << 6;
        uint32_t b = sb + st * STG;
#pragma unroll
        for (int i = 0; i < 4; i++) {
            int c = tid + i * 256, m = c >> 3, k8 = c & 7;
            size_t off = (size_t)(m0 + m) * ND + kk + k8 * 8;
            uint32_t d = swz(m, k8);
            cpa(b + d, Ah + off);
            cpa(b + OFF_AL + d, Al + off);
        }
#pragma unroll
        for (int i = 0; i < 2; i++) {
            int c = tid + i * 256, k = c >> 3, n8 = c & 7;
            size_t off = (size_t)(kk + k) * NF + n0 + n8 * 8;
            uint32_t d = swz(k, n8);
            cpa(b + OFF_BH + d, Bh + off);
            cpa(b + OFF_BL + d, Bl + off);
        }
        cpcommit();
    };

    float acc1[2][4][4] = {}, acc2[2][4][4] = {};
    load(0, 0);
    const int ITERS = ND / 64;  // 16
    for (int it = 0; it < ITERS; it++) {
        if (it + 1 < ITERS) { load(it + 1, (it + 1) & 1); cpwait1(); } else cpwait0();
        __syncthreads();
        stage3_nn(sb + (it & 1) * STG, wm, wn, lane, acc1, acc2);
        __syncthreads();
    }

    float* C = g_proj[z]; hf* Ph = g_ph[z]; hf* Pl = g_pl[z];
    int g = lane >> 2, tg = lane & 3;
#pragma unroll
    for (int mt = 0; mt < 2; mt++)
#pragma unroll
        for (int nt = 0; nt < 4; nt++) {
            int col = n0 + wn * 32 + nt * 8 + tg * 2;
            float bz0 = bias[col], bz1 = bias[col + 1];
#pragma unroll
            for (int hh = 0; hh < 2; hh++) {
                int row = m0 + wm * 32 + mt * 16 + g + hh * 8;
                float v0 = acc1[mt][nt][hh * 2 + 0] + acc2[mt][nt][hh * 2 + 0] * INV_SCL + bz0;
                float v1 = acc1[mt][nt][hh * 2 + 1] + acc2[mt][nt][hh * 2 + 1] * INV_SCL + bz1;
                size_t off = (size_t)row * NF + col;
                *(float2*)(C + off) = make_float2(v0, v1);
                split2(Ph, Pl, off, v0, v1);
            }
        }
}

// ---------------- row norms ---------------------------------------------------
__global__ void __launch_bounds__(256) k_norm() {
    const int z = blockIdx.z;
    const int warp = threadIdx.x >> 5, lane = threadIdx.x & 31;
    const int row = blockIdx.x * 8 + warp;
    const float4* p = (const float4*)(g_proj[z] + (size_t)row * NF);
    float s = 0.f;
#pragma unroll
    for (int i = 0; i < 4; i++) {
        float4 v = p[lane + i * 32];
        s += v.x * v.x + v.y * v.y + v.z * v.z + v.w * v.w;
    }
#pragma unroll
    for (int o = 16; o; o >>= 1) s += __shfl_xor_sync(0xffffffffu, s, o);
    if (lane == 0) g_norm[z][row] = sqrtf(s);
}

// ---------------- sim GEMM (fused dual-acc NT, gathered rows) ----------------
__global__ void __launch_bounds__(256) k_sim_mma(int z) {
    const int cnt = g_cnt[z];
    const int m0 = blockIdx.y * 128;
    if (m0 >= cnt) return;
    const int n0 = blockIdx.x * 64;
    const hf* Ph = g_ph[z]; const hf* Pl = g_pl[z];

    extern __shared__ __align__(16) char sm[];
    const uint32_t sb = s2u(sm);
    const int tid = threadIdx.x, lane = tid & 31, warp = tid >> 5;
    const int wm = warp & 3, wn = warp >> 2;

    __shared__ int rows[128];
    if (tid < 128) {
        int mm = m0 + tid; if (mm >= cnt) mm = cnt - 1;
        rows[tid] = g_rows[z][mm];
    }
    __syncthreads();

    auto load = [&](int it, int st) {
        const int kk = it << 6;
        uint32_t b = sb + st * STG;
#pragma unroll
        for (int i = 0; i < 4; i++) {
            int c = tid + i * 256, m = c >> 3, k8 = c & 7;
            size_t off = (size_t)rows[m] * NF + kk + k8 * 8;
            uint32_t d = swz(m, k8);
            cpa(b + d, Ph + off);
            cpa(b + OFF_AL + d, Pl + off);
        }
#pragma unroll
        for (int i = 0; i < 2; i++) {
            int c = tid + i * 256, n = c >> 3, k8 = c & 7;
            size_t off = (size_t)(n0 + n) * NF + kk + k8 * 8;
            uint32_t d = swz(n, k8);
            cpa(b + OFF_BH + d, Ph + off);
            cpa(b + OFF_BL + d, Pl + off);
        }
        cpcommit();
    };

    float acc1[2][4][4] = {}, acc2[2][4][4] = {};
    load(0, 0);
    const int ITERS = NF / 64;  // 8
    for (int it = 0; it < ITERS; it++) {
        if (it + 1 < ITERS) { load(it + 1, (it + 1) & 1); cpwait1(); } else cpwait0();
        __syncthreads();
        stage3_nt(sb + (it & 1) * STG, wm, wn, lane, acc1, acc2);
        __syncthreads();
    }

    int g = lane >> 2, tg = lane & 3;
#pragma unroll
    for (int mt = 0; mt < 2; mt++)
#pragma unroll
        for (int nt = 0; nt < 4; nt++) {
            int col = n0 + wn * 32 + nt * 8 + tg * 2;
#pragma unroll
            for (int hh = 0; hh < 2; hh++) {
                int m = m0 + wm * 32 + mt * 16 + g + hh * 8;
                if (m < cnt)
                    *(float2*)(g_sim + (size_t)m * NB + col) = make_float2(
                        acc1[mt][nt][hh * 2 + 0] + acc2[mt][nt][hh * 2 + 0] * INV_SCL,
                        acc1[mt][nt][hh * 2 + 1] + acc2[mt][nt][hh * 2 + 1] * INV_SCL);
            }
        }
}

// ---------------- top-3 via approx top-8 + exact fp32 rescoring ---------------
__device__ __forceinline__ bool better(float v, int i, float V, int I) {
    return v > V || (v == V && i < I);  // jax top_k tie-break: lower index wins
}

__global__ void __launch_bounds__(128) k_topk(int z, const int* __restrict__ mi) {
    const int m = blockIdx.x;
    const int cnt = g_cnt[z];
    if (m >= cnt) return;
    const int r = g_rows[z][m];
    float* P = g_proj[z];
    hf* Ph = g_ph[z]; hf* Pl = g_pl[z];
    const float* nrm = g_norm[z];
    const float ni = nrm[r];
    const float* srow = g_sim + (size_t)m * NB;
    const int tid = threadIdx.x;

    // phase 1: per-thread approx top-3 over strided columns
    float v0 = NEG_INF, v1 = NEG_INF, v2 = NEG_INF;
    int   i0 = NB, i1 = NB, i2 = NB;
    for (int n = tid; n < NB; n += 128) {
        if (mi[n] == z + 1) continue;  // missing columns excluded (incl. self)
        float s = srow[n] / fmaxf(ni * nrm[n], 1e-8f);
        if (better(s, n, v0, i0)) { v2 = v1; i2 = i1; v1 = v0; i1 = i0; v0 = s; i0 = n; }
        else if (better(s, n, v1, i1)) { v2 = v1; i2 = i1; v1 = s; i1 = n; }
        else if (better(s, n, v2, i2)) { v2 = s; i2 = n; }
    }

    __shared__ float sv[384];
    __shared__ int   si[384];
    sv[tid * 3 + 0] = v0; si[tid * 3 + 0] = i0;
    sv[tid * 3 + 1] = v1; si[tid * 3 + 1] = i1;
    sv[tid * 3 + 2] = v2; si[tid * 3 + 2] = i2;
    __syncthreads();

    // phase 2: merge union -> approx top-8 candidate set
    __shared__ int cand[8];
    if (tid == 0) {
        float bv[8]; int bx[8];
#pragma unroll
        for (int j = 0; j < 8; j++) { bv[j] = NEG_INF; bx[j] = NB; }
        for (int t = 0; t < 384; t++) {
            float s = sv[t]; int n = si[t];
            if (n >= NB) continue;
            if (better(s, n, bv[7], bx[7])) {
                int j = 7;
                while (j > 0 && better(s, n, bv[j - 1], bx[j - 1])) {
                    bv[j] = bv[j - 1]; bx[j] = bx[j - 1]; j--;
                }
                bv[j] = s; bx[j] = n;
            }
        }
#pragma unroll
        for (int j = 0; j < 8; j++) cand[j] = bx[j];
    }
    __syncthreads();

    // phase 3: exact fp32 cosine sims for the 8 candidates (deterministic tree sum)
    __shared__ float cval[8];
    const int warp = tid >> 5, lane = tid & 31;
    const float* pr = P + (size_t)r * NF;
    for (int c = warp; c < 8; c += 4) {
        int n = cand[c];
        if (n >= NB) { if (lane == 0) cval[c] = NEG_INF; continue; }
        const float* pc = P + (size_t)n * NF;
        float s = 0.f;
#pragma unroll 4
        for (int f = lane; f < NF; f += 32) s += pr[f] * pc[f];
#pragma unroll
        for (int o = 16; o; o >>= 1) s += __shfl_xor_sync(0xffffffffu, s, o);
        if (lane == 0) cval[c] = s / fmaxf(ni * nrm[n], 1e-8f);
    }
    __syncthreads();

    // phase 4: exact top-3 of the 8 + softmax
    __shared__ float w[3];
    __shared__ int   bi[3];
    if (tid == 0) {
        float b0 = NEG_INF, b1 = NEG_INF, b2 = NEG_INF;
        int   j0 = NB, j1 = NB, j2 = NB;
        for (int t = 0; t < 8; t++) {
            float s = cval[t]; int n = cand[t];
            if (n >= NB) continue;
            if (better(s, n, b0, j0)) { b2 = b1; j2 = j1; b1 = b0; j1 = j0; b0 = s; j0 = n; }
            else if (better(s, n, b1, j1)) { b2 = b1; j2 = j1; b1 = s; j1 = n; }
            else if (better(s, n, b2, j2)) { b2 = s; j2 = n; }
        }
        float e0 = 1.0f, e1 = expf(b1 - b0), e2 = expf(b2 - b0);
        float inv = 1.0f / (e0 + e1 + e2);
        w[0] = e0 * inv; w[1] = e1 * inv; w[2] = e2 * inv;
        bi[0] = j0; bi[1] = j1; bi[2] = j2;
    }
    __syncthreads();

    // phase 5: weighted fill + refresh fp16 splits
    const float* f0 = P + (size_t)bi[0] * NF;
    const float* f1 = P + (size_t)bi[1] * NF;
    const float* f2 = P + (size_t)bi[2] * NF;
    const float w0 = w[0], w1 = w[1], w2 = w[2];
    for (int f = tid * 2; f < NF; f += 256) {
        float a0 = w0 * f0[f]     + w1 * f1[f]     + w2 * f2[f];
        float a1 = w0 * f0[f + 1] + w1 * f1[f + 1] + w2 * f2[f + 1];
        size_t off = (size_t)r * NF + f;
        *(float2*)(P + off) = make_float2(a0, a1);
        split2(Ph, Pl, off, a0, a1);
    }
}

// ---------------- fused concat GEMM + ReLU (dual-acc fp16 split) -------------
__global__ void __launch_bounds__(256) k_h_mma(const float* __restrict__ b1) {
    const int m0 = blockIdx.y * 128, n0 = blockIdx.x * 64;
    extern __shared__ __align__(16) char sm[];
    const uint32_t sb = s2u(sm);
    const int tid = threadIdx.x, lane = tid & 31, warp = tid >> 5;
    const int wm = warp & 3, wn = warp >> 2;

    auto load = [&](int it, int st) {
        const int mod = it >> 3, kk = (it & 7) << 6;
        const hf* Ah = g_ph[mod]; const hf* Al = g_pl[mod];
        uint32_t b = sb + st * STG;
#pragma unroll
        for (int i = 0; i < 4; i++) {
            int c = tid + i * 256, m = c >> 3, k8 = c & 7;
            size_t off = (size_t)(m0 + m) * NF + kk + k8 * 8;
            uint32_t d = swz(m, k8);
            cpa(b + d, Ah + off);
            cpa(b + OFF_AL + d, Al + off);
        }
#pragma unroll
        for (int i = 0; i < 2; i++) {
            int c = tid + i * 256, k = c >> 3, n8 = c & 7;
            size_t off = (size_t)(mod * NF + kk + k) * NF + n0 + n8 * 8;
            uint32_t d = swz(k, n8);
            cpa(b + OFF_BH + d, g_w1h + off);
            cpa(b + OFF_BL + d, g_w1l + off);
        }
        cpcommit();
    };

    float acc1[2][4][4] = {}, acc2[2][4][4] = {};
    load(0, 0);
    const int ITERS = 24;  // 3 modalities x 8 BK-tiles
    for (int it = 0; it < ITERS; it++) {
        if (it + 1 < ITERS) { load(it + 1, (it + 1) & 1); cpwait1(); } else cpwait0();
        __syncthreads();
        stage3_nn(sb + (it & 1) * STG, wm, wn, lane, acc1, acc2);
        __syncthreads();
    }

    int g = lane >> 2, tg = lane & 3;
#pragma unroll
    for (int mt = 0; mt < 2; mt++)
#pragma unroll
        for (int nt = 0; nt < 4; nt++) {
            int col = n0 + wn * 32 + nt * 8 + tg * 2;
            float bz0 = b1[col], bz1 = b1[col + 1];
#pragma unroll
            for (int hh = 0; hh < 2; hh++) {
                int row = m0 + wm * 32 + mt * 16 + g + hh * 8;
                float v0 = fmaxf(acc1[mt][nt][hh * 2 + 0] + acc2[mt][nt][hh * 2 + 0] * INV_SCL + bz0, 0.f);
                float v1 = fmaxf(acc1[mt][nt][hh * 2 + 1] + acc2[mt][nt][hh * 2 + 1] * INV_SCL + bz1, 0.f);
                *(float2*)(g_h + (size_t)row * NF + col) = make_float2(v0, v1);
            }
        }
}

// ---------------- out[m] = h[m,:] . W2 + b2 ----------------------------------
__global__ void __launch_bounds__(128) k_out(const float* __restrict__ W2,
                                             const float* __restrict__ b2,
                                             float* __restrict__ out) {
    const int m = blockIdx.x;
    float s = 0.f;
    for (int n = threadIdx.x; n < NF; n += 128)
        s += g_h[(size_t)m * NF + n] * W2[n];
#pragma unroll
    for (int o = 16; o; o >>= 1) s += __shfl_xor_sync(0xffffffffu, s, o);
    __shared__ float ps[4];
    if ((threadIdx.x & 31) == 0) ps[threadIdx.x >> 5] = s;
    __syncthreads();
    if (threadIdx.x == 0) out[m] = ps[0] + ps[1] + ps[2] + ps[3] + b2[0];
}

// ---------------- launcher ----------------------------------------------------
extern "C" void kernel_launch(void* const* d_in, const int* in_sizes, int n_in,
                              void* d_out, int out_size) {
    const float* lang = (const float*)d_in[0];
    const float* vid  = (const float*)d_in[1];
    const float* aud  = (const float*)d_in[2];
    const int*   mi   = (const int*)d_in[3];
    const float* Wl   = (const float*)d_in[4];
    const float* bl   = (const float*)d_in[5];
    const float* Wv   = (const float*)d_in[6];
    const float* bv   = (const float*)d_in[7];
    const float* Wa   = (const float*)d_in[8];
    const float* ba   = (const float*)d_in[9];
    const float* W1   = (const float*)d_in[10];
    const float* b1   = (const float*)d_in[11];
    const float* W2   = (const float*)d_in[12];
    const float* b2   = (const float*)d_in[13];
    float* out = (float*)d_out;

    cudaFuncSetAttribute(k_proj_mma, cudaFuncAttributeMaxDynamicSharedMemorySize, DSM);
    cudaFuncSetAttribute(k_sim_mma,  cudaFuncAttributeMaxDynamicSharedMemorySize, DSM);
    cudaFuncSetAttribute(k_h_mma,    cudaFuncAttributeMaxDynamicSharedMemorySize, DSM);

    k_reset<<<1, 32>>>();
    k_build<<<NB / 256, 256>>>(mi);

    k_split<<<(NB * ND / 4) / 256, 256>>>(lang, 0, NB * ND / 4);
    k_split<<<(NB * ND / 4) / 256, 256>>>(vid,  1, NB * ND / 4);
    k_split<<<(NB * ND / 4) / 256, 256>>>(aud,  2, NB * ND / 4);
    k_split<<<(ND * NF / 4) / 256, 256>>>(Wl,   3, ND * NF / 4);
    k_split<<<(ND * NF / 4) / 256, 256>>>(Wv,   4, ND * NF / 4);
    k_split<<<(ND * NF / 4) / 256, 256>>>(Wa,   5, ND * NF / 4);
    k_split<<<(3 * NF * NF / 4) / 256, 256>>>(W1, 6, 3 * NF * NF / 4);

    k_proj_mma<<<dim3(NF / 64, NB / 128, 3), 256, DSM>>>(bl, bv, ba);
    k_norm<<<dim3(NB / 8, 1, 3), 256>>>();

    for (int z = 0; z < 3; z++) {
        k_sim_mma<<<dim3(NB / 64, NB / 128), 256, DSM>>>(z);
        k_topk<<<NB, 128>>>(z, mi);
    }

    k_h_mma<<<dim3(NF / 64, NB / 128), 256, DSM>>>(b1);
    k_out<<<NB, 128>>>(W2, b2, out);
}

// round 8
// speedup vs baseline: 3.4295x; 1.2654x over previous
#include <cuda_runtime.h>
#include <cuda_fp16.h>
#include <cstdint>

#define NB 4096
#define ND 1024
#define NF 512
#define NEG_INF (-1e30f)
#define SCL 2048.0f
#define INV_SCL (1.0f / 2048.0f)

typedef __half hf;

// ---------------- scratch (device globals; no allocations allowed) ----------
__device__ float g_proj[3][NB * NF];          // fp32 projections (filled in place)
__device__ float g_norm[3][NB];
__device__ int   g_rows[3][NB];
__device__ int   g_cnt[3];
__device__ float g_sim[3][(size_t)NB * NB];   // per-modality sim scratch
__device__ float g_h[(size_t)NB * NF];

__device__ hf g_xh[3][NB * ND], g_xl[3][NB * ND];   // fp16 scaled splits of inputs
__device__ hf g_wh[3][ND * NF], g_wl[3][ND * NF];   // proj weights
__device__ hf g_w1h[3 * NF * NF], g_w1l[3 * NF * NF];
__device__ hf g_ph[3][NB * NF], g_pl[3][NB * NF];   // projections

// ---------------- PTX helpers ------------------------------------------------
__device__ __forceinline__ uint32_t s2u(const void* p) {
    return (uint32_t)__cvta_generic_to_shared(p);
}
__device__ __forceinline__ void cpa(uint32_t dst, const void* src) {
    asm volatile("cp.async.cg.shared.global [%0], [%1], 16;\n" :: "r"(dst), "l"(src));
}
__device__ __forceinline__ void cpcommit() { asm volatile("cp.async.commit_group;\n"); }
__device__ __forceinline__ void cpwait1()  { asm volatile("cp.async.wait_group 1;\n"); }
__device__ __forceinline__ void cpwait0()  { asm volatile("cp.async.wait_group 0;\n"); }
__device__ __forceinline__ void ldsm4(uint32_t* r, uint32_t a) {
    asm volatile("ldmatrix.sync.aligned.m8n8.x4.shared.b16 {%0,%1,%2,%3}, [%4];\n"
                 : "=r"(r[0]), "=r"(r[1]), "=r"(r[2]), "=r"(r[3]) : "r"(a));
}
__device__ __forceinline__ void ldsm4t(uint32_t* r, uint32_t a) {
    asm volatile("ldmatrix.sync.aligned.m8n8.x4.trans.shared.b16 {%0,%1,%2,%3}, [%4];\n"
                 : "=r"(r[0]), "=r"(r[1]), "=r"(r[2]), "=r"(r[3]) : "r"(a));
}
__device__ __forceinline__ void mma_f16(float* c, const uint32_t* a, const uint32_t* b) {
    asm volatile("mma.sync.aligned.m16n8k16.row.col.f32.f16.f16.f32 "
                 "{%0,%1,%2,%3},{%4,%5,%6,%7},{%8,%9},{%0,%1,%2,%3};\n"
                 : "+f"(c[0]), "+f"(c[1]), "+f"(c[2]), "+f"(c[3])
                 : "r"(a[0]), "r"(a[1]), "r"(a[2]), "r"(a[3]), "r"(b[0]), "r"(b[1]));
}
// 128B smem rows, xor-swizzle of 16B chunks -> conflict-free ldmatrix
__device__ __forceinline__ uint32_t swz(uint32_t row, uint32_t chunk) {
    return row * 128u + ((chunk ^ (row & 7u)) * 16u);
}

// fused-stage smem layout (per stage): AH 16KB | AL 16KB | BH 8KB | BL 8KB
#define OFF_AL 16384
#define OFF_BH 32768
#define OFF_BL 40960
#define STG    49152
#define DSM    (2 * STG)

// hi-only sim stage layout: AH 16KB | BH 8KB
#define SOFF_B 16384
#define SSTG   24576
#define SDSM   (2 * SSTG)

// one BK=64 stage: acc1 += Ah*Bh ; acc2 += Al*Bh + Ah*Bl  (acc2 scaled 2^-11 later)
// NN: A m-major (non-trans), B k-major (trans ldsm)
__device__ __forceinline__ void stage3_nn(uint32_t base, int wm, int wn, int lane,
                                          float (&acc1)[2][4][4], float (&acc2)[2][4][4]) {
#pragma unroll
    for (int ks = 0; ks < 4; ks++) {
        uint32_t ah[2][4], al[2][4];
#pragma unroll
        for (int mt = 0; mt < 2; mt++) {
            uint32_t m_l = wm * 32 + mt * 16 + (lane & 15);
            uint32_t c = ks * 2 + (lane >> 4);
            ldsm4(ah[mt], base + swz(m_l, c));
            ldsm4(al[mt], base + OFF_AL + swz(m_l, c));
        }
        uint32_t bh[4][2], bl[4][2];
#pragma unroll
        for (int j = 0; j < 2; j++) {
            uint32_t k_l = ks * 16 + (lane & 15);
            uint32_t c = wn * 4 + j * 2 + (lane >> 4);
            uint32_t r[4];
            ldsm4t(r, base + OFF_BH + swz(k_l, c));
            bh[j * 2][0] = r[0]; bh[j * 2][1] = r[1];
            bh[j * 2 + 1][0] = r[2]; bh[j * 2 + 1][1] = r[3];
            ldsm4t(r, base + OFF_BL + swz(k_l, c));
            bl[j * 2][0] = r[0]; bl[j * 2][1] = r[1];
            bl[j * 2 + 1][0] = r[2]; bl[j * 2 + 1][1] = r[3];
        }
#pragma unroll
        for (int mt = 0; mt < 2; mt++)
#pragma unroll
            for (int nt = 0; nt < 4; nt++) {
                mma_f16(acc1[mt][nt], ah[mt], bh[nt]);
                mma_f16(acc2[mt][nt], al[mt], bh[nt]);
                mma_f16(acc2[mt][nt], ah[mt], bl[nt]);
            }
    }
}

// hi-only NT stage: acc += Ah*Bh.  A m-major, B n-major (non-trans ldsm)
__device__ __forceinline__ void stage1_nt(uint32_t base, int wm, int wn, int lane,
                                          float (&acc)[2][4][4]) {
#pragma unroll
    for (int ks = 0; ks < 4; ks++) {
        uint32_t ah[2][4];
#pragma unroll
        for (int mt = 0; mt < 2; mt++) {
            uint32_t m_l = wm * 32 + mt * 16 + (lane & 15);
            ldsm4(ah[mt], base + swz(m_l, ks * 2 + (lane >> 4)));
        }
        uint32_t bh[4][2];
#pragma unroll
        for (int j = 0; j < 2; j++) {
            uint32_t n_l = wn * 32 + j * 16 + (lane & 7) + ((lane >> 4) << 3);
            uint32_t r[4];
            ldsm4(r, base + SOFF_B + swz(n_l, ks * 2 + ((lane >> 3) & 1)));
            bh[j * 2][0] = r[0]; bh[j * 2][1] = r[1];
            bh[j * 2 + 1][0] = r[2]; bh[j * 2 + 1][1] = r[3];
        }
#pragma unroll
        for (int mt = 0; mt < 2; mt++)
#pragma unroll
            for (int nt = 0; nt < 4; nt++) mma_f16(acc[mt][nt], ah[mt], bh[nt]);
    }
}

// ---------------- tiny setup kernels -----------------------------------------
__global__ void k_reset() { if (threadIdx.x < 3) g_cnt[threadIdx.x] = 0; }

__global__ void k_build(const int* __restrict__ mi) {
    int i = blockIdx.x * blockDim.x + threadIdx.x;
    if (i < NB) {
        int t = mi[i];
        if (t >= 1 && t <= 3) { int p = atomicAdd(&g_cnt[t - 1], 1); g_rows[t - 1][p] = i; }
    }
}

// fp32 -> fp16 scaled hi/lo split:  x = h + l/2048,  h=fp16(x), l=fp16((x-h)*2048)
__global__ void __launch_bounds__(256) k_split(const float* __restrict__ src, int which, int n4) {
    hf *h, *l;
    switch (which) {
        case 0: h = g_xh[0]; l = g_xl[0]; break;
        case 1: h = g_xh[1]; l = g_xl[1]; break;
        case 2: h = g_xh[2]; l = g_xl[2]; break;
        case 3: h = g_wh[0]; l = g_wl[0]; break;
        case 4: h = g_wh[1]; l = g_wl[1]; break;
        case 5: h = g_wh[2]; l = g_wl[2]; break;
        default: h = g_w1h;  l = g_w1l;  break;
    }
    int i = blockIdx.x * 256 + threadIdx.x;
    if (i >= n4) return;
    float4 v = ((const float4*)src)[i];
    hf h0 = __float2half_rn(v.x), h1 = __float2half_rn(v.y);
    hf h2 = __float2half_rn(v.z), h3 = __float2half_rn(v.w);
    __half2* H = (__half2*)h;
    __half2* L = (__half2*)l;
    H[2 * i]     = __halves2half2(h0, h1);
    H[2 * i + 1] = __halves2half2(h2, h3);
    L[2 * i]     = __halves2half2(__float2half_rn((v.x - __half2float(h0)) * SCL),
                                  __float2half_rn((v.y - __half2float(h1)) * SCL));
    L[2 * i + 1] = __halves2half2(__float2half_rn((v.z - __half2float(h2)) * SCL),
                                  __float2half_rn((v.w - __half2float(h3)) * SCL));
}

__device__ __forceinline__ void split2(hf* Ph, hf* Pl, size_t off, float v0, float v1) {
    hf h0 = __float2half_rn(v0), h1 = __float2half_rn(v1);
    *(__half2*)(Ph + off) = __halves2half2(h0, h1);
    *(__half2*)(Pl + off) = __halves2half2(
        __float2half_rn((v0 - __half2float(h0)) * SCL),
        __float2half_rn((v1 - __half2float(h1)) * SCL));
}

// ---------------- projection GEMM (fused dual-acc fp16 split) ----------------
__global__ void __launch_bounds__(256) k_proj_mma(const float* __restrict__ bl,
                                                  const float* __restrict__ bv,
                                                  const float* __restrict__ ba) {
    const int z = blockIdx.z;
    const hf* Ah = g_xh[z]; const hf* Al = g_xl[z];
    const hf* Bh = g_wh[z]; const hf* Bl = g_wl[z];
    const float* bias = (z == 0) ? bl : (z == 1) ? bv : ba;
    const int m0 = blockIdx.y * 128, n0 = blockIdx.x * 64;

    extern __shared__ __align__(16) char sm[];
    const uint32_t sb = s2u(sm);
    const int tid = threadIdx.x, lane = tid & 31, warp = tid >> 5;
    const int wm = warp & 3, wn = warp >> 2;

    auto load = [&](int it, int st) {
        const int kk = it << 6;
        uint32_t b = sb + st * STG;
#pragma unroll
        for (int i = 0; i < 4; i++) {
            int c = tid + i * 256, m = c >> 3, k8 = c & 7;
            size_t off = (size_t)(m0 + m) * ND + kk + k8 * 8;
            uint32_t d = swz(m, k8);
            cpa(b + d, Ah + off);
            cpa(b + OFF_AL + d, Al + off);
        }
#pragma unroll
        for (int i = 0; i < 2; i++) {
            int c = tid + i * 256, k = c >> 3, n8 = c & 7;
            size_t off = (size_t)(kk + k) * NF + n0 + n8 * 8;
            uint32_t d = swz(k, n8);
            cpa(b + OFF_BH + d, Bh + off);
            cpa(b + OFF_BL + d, Bl + off);
        }
        cpcommit();
    };

    float acc1[2][4][4] = {}, acc2[2][4][4] = {};
    load(0, 0);
    const int ITERS = ND / 64;  // 16
    for (int it = 0; it < ITERS; it++) {
        if (it + 1 < ITERS) { load(it + 1, (it + 1) & 1); cpwait1(); } else cpwait0();
        __syncthreads();
        stage3_nn(sb + (it & 1) * STG, wm, wn, lane, acc1, acc2);
        __syncthreads();
    }

    float* C = g_proj[z]; hf* Ph = g_ph[z]; hf* Pl = g_pl[z];
    int g = lane >> 2, tg = lane & 3;
#pragma unroll
    for (int mt = 0; mt < 2; mt++)
#pragma unroll
        for (int nt = 0; nt < 4; nt++) {
            int col = n0 + wn * 32 + nt * 8 + tg * 2;
            float bz0 = bias[col], bz1 = bias[col + 1];
#pragma unroll
            for (int hh = 0; hh < 2; hh++) {
                int row = m0 + wm * 32 + mt * 16 + g + hh * 8;
                float v0 = acc1[mt][nt][hh * 2 + 0] + acc2[mt][nt][hh * 2 + 0] * INV_SCL + bz0;
                float v1 = acc1[mt][nt][hh * 2 + 1] + acc2[mt][nt][hh * 2 + 1] * INV_SCL + bz1;
                size_t off = (size_t)row * NF + col;
                *(float2*)(C + off) = make_float2(v0, v1);
                split2(Ph, Pl, off, v0, v1);
            }
        }
}

// ---------------- row norms ---------------------------------------------------
__global__ void __launch_bounds__(256) k_norm() {
    const int z = blockIdx.z;
    const int warp = threadIdx.x >> 5, lane = threadIdx.x & 31;
    const int row = blockIdx.x * 8 + warp;
    const float4* p = (const float4*)(g_proj[z] + (size_t)row * NF);
    float s = 0.f;
#pragma unroll
    for (int i = 0; i < 4; i++) {
        float4 v = p[lane + i * 32];
        s += v.x * v.x + v.y * v.y + v.z * v.z + v.w * v.w;
    }
#pragma unroll
    for (int o = 16; o; o >>= 1) s += __shfl_xor_sync(0xffffffffu, s, o);
    if (lane == 0) g_norm[z][row] = sqrtf(s);
}

// ---------------- sim GEMM (hi-only NT, gathered rows, z-parallel) -----------
__global__ void __launch_bounds__(256) k_sim_mma() {
    const int z = blockIdx.z;
    const int cnt = g_cnt[z];
    const int m0 = blockIdx.y * 128;
    if (m0 >= cnt) return;
    const int n0 = blockIdx.x * 64;
    const hf* Ph = g_ph[z];

    extern __shared__ __align__(16) char sm[];
    const uint32_t sb = s2u(sm);
    const int tid = threadIdx.x, lane = tid & 31, warp = tid >> 5;
    const int wm = warp & 3, wn = warp >> 2;

    __shared__ int rows[128];
    if (tid < 128) {
        int mm = m0 + tid; if (mm >= cnt) mm = cnt - 1;
        rows[tid] = g_rows[z][mm];
    }
    __syncthreads();

    auto load = [&](int it, int st) {
        const int kk = it << 6;
        uint32_t b = sb + st * SSTG;
#pragma unroll
        for (int i = 0; i < 4; i++) {
            int c = tid + i * 256, m = c >> 3, k8 = c & 7;
            cpa(b + swz(m, k8), Ph + (size_t)rows[m] * NF + kk + k8 * 8);
        }
#pragma unroll
        for (int i = 0; i < 2; i++) {
            int c = tid + i * 256, n = c >> 3, k8 = c & 7;
            cpa(b + SOFF_B + swz(n, k8), Ph + (size_t)(n0 + n) * NF + kk + k8 * 8);
        }
        cpcommit();
    };

    float acc[2][4][4] = {};
    load(0, 0);
    const int ITERS = NF / 64;  // 8
    for (int it = 0; it < ITERS; it++) {
        if (it + 1 < ITERS) { load(it + 1, (it + 1) & 1); cpwait1(); } else cpwait0();
        __syncthreads();
        stage1_nt(sb + (it & 1) * SSTG, wm, wn, lane, acc);
        __syncthreads();
    }

    float* S = g_sim[z];
    int g = lane >> 2, tg = lane & 3;
#pragma unroll
    for (int mt = 0; mt < 2; mt++)
#pragma unroll
        for (int nt = 0; nt < 4; nt++) {
            int col = n0 + wn * 32 + nt * 8 + tg * 2;
#pragma unroll
            for (int hh = 0; hh < 2; hh++) {
                int m = m0 + wm * 32 + mt * 16 + g + hh * 8;
                if (m < cnt)
                    *(float2*)(S + (size_t)m * NB + col) =
                        make_float2(acc[mt][nt][hh * 2 + 0], acc[mt][nt][hh * 2 + 1]);
            }
        }
}

// ---------------- top-3 via approx top-8 + exact fp32 rescoring ---------------
__device__ __forceinline__ bool better(float v, int i, float V, int I) {
    return v > V || (v == V && i < I);  // jax top_k tie-break: lower index wins
}

__global__ void __launch_bounds__(128) k_topk(const int* __restrict__ mi) {
    const int z = blockIdx.z;
    const int m = blockIdx.x;
    const int cnt = g_cnt[z];
    if (m >= cnt) return;
    const int r = g_rows[z][m];
    float* P = g_proj[z];
    hf* Ph = g_ph[z]; hf* Pl = g_pl[z];
    const float* nrm = g_norm[z];
    const float ni = nrm[r];
    const float* srow = g_sim[z] + (size_t)m * NB;
    const int tid = threadIdx.x;

    // phase 1: per-thread approx top-3 over strided columns
    float v0 = NEG_INF, v1 = NEG_INF, v2 = NEG_INF;
    int   i0 = NB, i1 = NB, i2 = NB;
    for (int n = tid; n < NB; n += 128) {
        if (mi[n] == z + 1) continue;  // missing columns excluded (incl. self)
        float s = srow[n] / fmaxf(ni * nrm[n], 1e-8f);
        if (better(s, n, v0, i0)) { v2 = v1; i2 = i1; v1 = v0; i1 = i0; v0 = s; i0 = n; }
        else if (better(s, n, v1, i1)) { v2 = v1; i2 = i1; v1 = s; i1 = n; }
        else if (better(s, n, v2, i2)) { v2 = s; i2 = n; }
    }

    __shared__ float sv[384];
    __shared__ int   si[384];
    sv[tid * 3 + 0] = v0; si[tid * 3 + 0] = i0;
    sv[tid * 3 + 1] = v1; si[tid * 3 + 1] = i1;
    sv[tid * 3 + 2] = v2; si[tid * 3 + 2] = i2;
    __syncthreads();

    // phase 2: merge union -> approx top-8 candidate set
    __shared__ int cand[8];
    if (tid == 0) {
        float bv[8]; int bx[8];
#pragma unroll
        for (int j = 0; j < 8; j++) { bv[j] = NEG_INF; bx[j] = NB; }
        for (int t = 0; t < 384; t++) {
            float s = sv[t]; int n = si[t];
            if (n >= NB) continue;
            if (better(s, n, bv[7], bx[7])) {
                int j = 7;
                while (j > 0 && better(s, n, bv[j - 1], bx[j - 1])) {
                    bv[j] = bv[j - 1]; bx[j] = bx[j - 1]; j--;
                }
                bv[j] = s; bx[j] = n;
            }
        }
#pragma unroll
        for (int j = 0; j < 8; j++) cand[j] = bx[j];
    }
    __syncthreads();

    // phase 3: exact fp32 cosine sims for the 8 candidates (deterministic tree sum)
    __shared__ float cval[8];
    const int warp = tid >> 5, lane = tid & 31;
    const float* pr = P + (size_t)r * NF;
    for (int c = warp; c < 8; c += 4) {
        int n = cand[c];
        if (n >= NB) { if (lane == 0) cval[c] = NEG_INF; continue; }
        const float* pc = P + (size_t)n * NF;
        float s = 0.f;
#pragma unroll 4
        for (int f = lane; f < NF; f += 32) s += pr[f] * pc[f];
#pragma unroll
        for (int o = 16; o; o >>= 1) s += __shfl_xor_sync(0xffffffffu, s, o);
        if (lane == 0) cval[c] = s / fmaxf(ni * nrm[n], 1e-8f);
    }
    __syncthreads();

    // phase 4: exact top-3 of the 8 + softmax
    __shared__ float w[3];
    __shared__ int   bi[3];
    if (tid == 0) {
        float b0 = NEG_INF, b1 = NEG_INF, b2 = NEG_INF;
        int   j0 = NB, j1 = NB, j2 = NB;
        for (int t = 0; t < 8; t++) {
            float s = cval[t]; int n = cand[t];
            if (n >= NB) continue;
            if (better(s, n, b0, j0)) { b2 = b1; j2 = j1; b1 = b0; j1 = j0; b0 = s; j0 = n; }
            else if (better(s, n, b1, j1)) { b2 = b1; j2 = j1; b1 = s; j1 = n; }
            else if (better(s, n, b2, j2)) { b2 = s; j2 = n; }
        }
        float e0 = 1.0f, e1 = expf(b1 - b0), e2 = expf(b2 - b0);
        float inv = 1.0f / (e0 + e1 + e2);
        w[0] = e0 * inv; w[1] = e1 * inv; w[2] = e2 * inv;
        bi[0] = j0; bi[1] = j1; bi[2] = j2;
    }
    __syncthreads();

    // phase 5: weighted fill + refresh fp16 splits
    const float* f0 = P + (size_t)bi[0] * NF;
    const float* f1 = P + (size_t)bi[1] * NF;
    const float* f2 = P + (size_t)bi[2] * NF;
    const float w0 = w[0], w1 = w[1], w2 = w[2];
    for (int f = tid * 2; f < NF; f += 256) {
        float a0 = w0 * f0[f]     + w1 * f1[f]     + w2 * f2[f];
        float a1 = w0 * f0[f + 1] + w1 * f1[f + 1] + w2 * f2[f + 1];
        size_t off = (size_t)r * NF + f;
        *(float2*)(P + off) = make_float2(a0, a1);
        split2(Ph, Pl, off, a0, a1);
    }
}

// ---------------- fused concat GEMM + ReLU (dual-acc fp16 split) -------------
__global__ void __launch_bounds__(256) k_h_mma(const float* __restrict__ b1) {
    const int m0 = blockIdx.y * 128, n0 = blockIdx.x * 64;
    extern __shared__ __align__(16) char sm[];
    const uint32_t sb = s2u(sm);
    const int tid = threadIdx.x, lane = tid & 31, warp = tid >> 5;
    const int wm = warp & 3, wn = warp >> 2;

    auto load = [&](int it, int st) {
        const int mod = it >> 3, kk = (it & 7) << 6;
        const hf* Ah = g_ph[mod]; const hf* Al = g_pl[mod];
        uint32_t b = sb + st * STG;
#pragma unroll
        for (int i = 0; i < 4; i++) {
            int c = tid + i * 256, m = c >> 3, k8 = c & 7;
            size_t off = (size_t)(m0 + m) * NF + kk + k8 * 8;
            uint32_t d = swz(m, k8);
            cpa(b + d, Ah + off);
            cpa(b + OFF_AL + d, Al + off);
        }
#pragma unroll
        for (int i = 0; i < 2; i++) {
            int c = tid + i * 256, k = c >> 3, n8 = c & 7;
            size_t off = (size_t)(mod * NF + kk + k) * NF + n0 + n8 * 8;
            uint32_t d = swz(k, n8);
            cpa(b + OFF_BH + d, g_w1h + off);
            cpa(b + OFF_BL + d, g_w1l + off);
        }
        cpcommit();
    };

    float acc1[2][4][4] = {}, acc2[2][4][4] = {};
    load(0, 0);
    const int ITERS = 24;  // 3 modalities x 8 BK-tiles
    for (int it = 0; it < ITERS; it++) {
        if (it + 1 < ITERS) { load(it + 1, (it + 1) & 1); cpwait1(); } else cpwait0();
        __syncthreads();
        stage3_nn(sb + (it & 1) * STG, wm, wn, lane, acc1, acc2);
        __syncthreads();
    }

    int g = lane >> 2, tg = lane & 3;
#pragma unroll
    for (int mt = 0; mt < 2; mt++)
#pragma unroll
        for (int nt = 0; nt < 4; nt++) {
            int col = n0 + wn * 32 + nt * 8 + tg * 2;
            float bz0 = b1[col], bz1 = b1[col + 1];
#pragma unroll
            for (int hh = 0; hh < 2; hh++) {
                int row = m0 + wm * 32 + mt * 16 + g + hh * 8;
                float v0 = fmaxf(acc1[mt][nt][hh * 2 + 0] + acc2[mt][nt][hh * 2 + 0] * INV_SCL + bz0, 0.f);
                float v1 = fmaxf(acc1[mt][nt][hh * 2 + 1] + acc2[mt][nt][hh * 2 + 1] * INV_SCL + bz1, 0.f);
                *(float2*)(g_h + (size_t)row * NF + col) = make_float2(v0, v1);
            }
        }
}

// ---------------- out[m] = h[m,:] . W2 + b2 ----------------------------------
__global__ void __launch_bounds__(128) k_out(const float* __restrict__ W2,
                                             const float* __restrict__ b2,
                                             float* __restrict__ out) {
    const int m = blockIdx.x;
    float s = 0.f;
    for (int n = threadIdx.x; n < NF; n += 128)
        s += g_h[(size_t)m * NF + n] * W2[n];
#pragma unroll
    for (int o = 16; o; o >>= 1) s += __shfl_xor_sync(0xffffffffu, s, o);
    __shared__ float ps[4];
    if ((threadIdx.x & 31) == 0) ps[threadIdx.x >> 5] = s;
    __syncthreads();
    if (threadIdx.x == 0) out[m] = ps[0] + ps[1] + ps[2] + ps[3] + b2[0];
}

// ---------------- launcher ----------------------------------------------------
extern "C" void kernel_launch(void* const* d_in, const int* in_sizes, int n_in,
                              void* d_out, int out_size) {
    const float* lang = (const float*)d_in[0];
    const float* vid  = (const float*)d_in[1];
    const float* aud  = (const float*)d_in[2];
    const int*   mi   = (const int*)d_in[3];
    const float* Wl   = (const float*)d_in[4];
    const float* bl   = (const float*)d_in[5];
    const float* Wv   = (const float*)d_in[6];
    const float* bv   = (const float*)d_in[7];
    const float* Wa   = (const float*)d_in[8];
    const float* ba   = (const float*)d_in[9];
    const float* W1   = (const float*)d_in[10];
    const float* b1   = (const float*)d_in[11];
    const float* W2   = (const float*)d_in[12];
    const float* b2   = (const float*)d_in[13];
    float* out = (float*)d_out;

    cudaFuncSetAttribute(k_proj_mma, cudaFuncAttributeMaxDynamicSharedMemorySize, DSM);
    cudaFuncSetAttribute(k_sim_mma,  cudaFuncAttributeMaxDynamicSharedMemorySize, SDSM);
    cudaFuncSetAttribute(k_h_mma,    cudaFuncAttributeMaxDynamicSharedMemorySize, DSM);

    k_reset<<<1, 32>>>();
    k_build<<<NB / 256, 256>>>(mi);

    k_split<<<(NB * ND / 4) / 256, 256>>>(lang, 0, NB * ND / 4);
    k_split<<<(NB * ND / 4) / 256, 256>>>(vid,  1, NB * ND / 4);
    k_split<<<(NB * ND / 4) / 256, 256>>>(aud,  2, NB * ND / 4);
    k_split<<<(ND * NF / 4) / 256, 256>>>(Wl,   3, ND * NF / 4);
    k_split<<<(ND * NF / 4) / 256, 256>>>(Wv,   4, ND * NF / 4);
    k_split<<<(ND * NF / 4) / 256, 256>>>(Wa,   5, ND * NF / 4);
    k_split<<<(3 * NF * NF / 4) / 256, 256>>>(W1, 6, 3 * NF * NF / 4);

    k_proj_mma<<<dim3(NF / 64, NB / 128, 3), 256, DSM>>>(bl, bv, ba);
    k_norm<<<dim3(NB / 8, 1, 3), 256>>>();

    k_sim_mma<<<dim3(NB / 64, NB / 128, 3), 256, SDSM>>>();
    k_topk<<<dim3(NB, 1, 3), 128>>>(mi);

    k_h_mma<<<dim3(NF / 64, NB / 128), 256, DSM>>>(b1);
    k_out<<<NB, 128>>>(W2, b2, out);
}